// round 3
// baseline (speedup 1.0000x reference)
#include <cuda_runtime.h>

#define N_NODES 8192
#define IN_F 256
#define OUT_F 64
#define ALPHA 0.3f
#define JSPLIT 8
#define ROWTILE 128
#define CHUNK 128
#define WPAD 68  // padded row length (floats) for Wh smem tile

// Device scratch (no allocations allowed)
__device__ float g_Wh[N_NODES * OUT_F];                 // 2 MB fp32
__device__ float g_src[N_NODES];
__device__ float g_dst[N_NODES];
__device__ float g_blockmax[128];
__device__ float g_pacc[JSPLIT][N_NODES][OUT_F];        // 16 MB partials
__device__ float g_pden[JSPLIT][N_NODES];

// ---------------------------------------------------------------------------
// Kernel 1: Wh = h @ W (fp32), src/dst projections, per-block dst max.
// SMEM-tiled GEMM: block = 64 rows x 64 feats, thread = 4x4 micro-tile.
// ---------------------------------------------------------------------------
__global__ __launch_bounds__(256) void wh_kernel(const float* __restrict__ h,
                                                 const float* __restrict__ W,
                                                 const float* __restrict__ a) {
    __shared__ float sh[64][WPAD];   // h tile [row][k]
    __shared__ float sW[64][64];     // W tile [k][f]
    __shared__ float dtile[64];
    const int tid = threadIdx.x;
    const int tx = tid & 15;         // feat group (4 feats)
    const int ty = tid >> 4;         // row group (4 rows)
    const int I0 = blockIdx.x * 64;

    float acc[4][4] = {};

    for (int kt = 0; kt < 4; kt++) {
        __syncthreads();
#pragma unroll
        for (int it = 0; it < 4; it++) {
            const int sidx = tid + it * 256;           // 1024 float4 slots
            const int r = sidx >> 4;
            const int c = (sidx & 15) << 2;
            const float4 hv = *reinterpret_cast<const float4*>(
                &h[(size_t)(I0 + r) * IN_F + kt * 64 + c]);
            *reinterpret_cast<float4*>(&sh[r][c]) = hv;
            const float4 wv = *reinterpret_cast<const float4*>(
                &W[(size_t)(kt * 64 + r) * OUT_F + c]);
            *reinterpret_cast<float4*>(&sW[r][c]) = wv;
        }
        __syncthreads();
#pragma unroll 4
        for (int k = 0; k < 64; k++) {
            const float4 wv = *reinterpret_cast<const float4*>(&sW[k][tx << 2]);
            float hr[4];
#pragma unroll
            for (int m = 0; m < 4; m++) hr[m] = sh[ty * 4 + m][k];
#pragma unroll
            for (int m = 0; m < 4; m++) {
                acc[m][0] += hr[m] * wv.x;
                acc[m][1] += hr[m] * wv.y;
                acc[m][2] += hr[m] * wv.z;
                acc[m][3] += hr[m] * wv.w;
            }
        }
    }

    const float4 as = *reinterpret_cast<const float4*>(&a[tx << 2]);
    const float4 ad = *reinterpret_cast<const float4*>(&a[OUT_F + (tx << 2)]);
#pragma unroll
    for (int m = 0; m < 4; m++) {
        const int row = I0 + ty * 4 + m;
        *reinterpret_cast<float4*>(&g_Wh[(size_t)row * OUT_F + (tx << 2)]) =
            make_float4(acc[m][0], acc[m][1], acc[m][2], acc[m][3]);
        float sp = acc[m][0] * as.x + acc[m][1] * as.y + acc[m][2] * as.z + acc[m][3] * as.w;
        float dp = acc[m][0] * ad.x + acc[m][1] * ad.y + acc[m][2] * ad.z + acc[m][3] * ad.w;
#pragma unroll
        for (int off = 1; off < 16; off <<= 1) {
            sp += __shfl_xor_sync(0xffffffffu, sp, off);
            dp += __shfl_xor_sync(0xffffffffu, dp, off);
        }
        if (tx == 0) {
            g_src[row] = sp;
            g_dst[row] = dp;
            dtile[ty * 4 + m] = dp;
        }
    }
    __syncthreads();
    if (tid == 0) {
        float mm = dtile[0];
        for (int q = 1; q < 64; q++) mm = fmaxf(mm, dtile[q]);
        g_blockmax[blockIdx.x] = mm;
    }
}

// ---------------------------------------------------------------------------
// Kernel 2: fused masked exp-attention + aggregation over a column slice.
// Block = 128 rows x 1024 cols. 512 threads (16 warps); warp owns 8 rows.
// Per 128-col chunk: stage Wh chunk in SMEM, ballot adj to bitmasks,
// lane-group-of-8 per row consumes set bits: acc += p * Wh_smem[j].
// proxy_i = lrelu(src_i + max dst) >= every logit -> single-pass softmax.
// ---------------------------------------------------------------------------
__global__ __launch_bounds__(512, 2) void attn_kernel(const float* __restrict__ adj) {
    __shared__ float Whs[CHUNK][WPAD];
    __shared__ float dst_s[CHUNK];
    __shared__ float bm[128];
    __shared__ float dmax_s;

    const int tid = threadIdx.x;
    const int w = tid >> 5;           // warp 0..15
    const int lane = tid & 31;
    const int g = lane >> 3;          // row-group 0..3
    const int s = lane & 7;           // feat slot (8 feats)
    const int rt = blockIdx.x >> 3;
    const int js = blockIdx.x & 7;
    const int I0 = rt * ROWTILE;
    const int jbase = js * (N_NODES / JSPLIT);

    // global dst max (proxy base)
    if (tid < 128) bm[tid] = g_blockmax[tid];
    __syncthreads();
    if (tid == 0) {
        float mm = bm[0];
        for (int q = 1; q < 128; q++) mm = fmaxf(mm, bm[q]);
        dmax_s = mm;
    }
    __syncthreads();
    const float dmax = dmax_s;

    float acc[2][8] = {};
    float den[2] = {0.f, 0.f};
    float srcr[2], proxy[2];
#pragma unroll
    for (int rg = 0; rg < 2; rg++) {
        const int row = I0 + w * 8 + rg * 4 + g;
        const float sv = __ldg(&g_src[row]);
        srcr[rg] = sv;
        const float e = sv + dmax;
        proxy[rg] = e > 0.f ? e : ALPHA * e;
    }

    const int NCH = (N_NODES / JSPLIT) / CHUNK;  // 8
    for (int ch = 0; ch < NCH; ch++) {
        __syncthreads();  // previous chunk's readers done
        const int jcol0 = jbase + ch * CHUNK;
        for (int idx = tid; idx < CHUNK * 16; idx += 512) {
            const int j = idx >> 4;
            const int q = (idx & 15) << 2;
            const float4 v = *reinterpret_cast<const float4*>(
                &g_Wh[(size_t)(jcol0 + j) * OUT_F + q]);
            *reinterpret_cast<float4*>(&Whs[j][q]) = v;
        }
        if (tid < CHUNK) dst_s[tid] = g_dst[jcol0 + tid];
        __syncthreads();

#pragma unroll
        for (int rg = 0; rg < 2; rg++) {
            const int rbase = I0 + w * 8 + rg * 4;
            float4 av[4];
#pragma unroll
            for (int m = 0; m < 4; m++)
                av[m] = __ldg(reinterpret_cast<const float4*>(
                            &adj[(size_t)(rbase + m) * N_NODES + jcol0]) + lane);
            unsigned bg[4];
#pragma unroll
            for (int m = 0; m < 4; m++) {
                const unsigned b0 = __ballot_sync(0xffffffffu, av[m].x != 0.f);
                const unsigned b1 = __ballot_sync(0xffffffffu, av[m].y != 0.f);
                const unsigned b2 = __ballot_sync(0xffffffffu, av[m].z != 0.f);
                const unsigned b3 = __ballot_sync(0xffffffffu, av[m].w != 0.f);
                if (g == m) { bg[0] = b0; bg[1] = b1; bg[2] = b2; bg[3] = b3; }
            }
            const float sv = srcr[rg];
            const float px = proxy[rg];
#pragma unroll
            for (int c = 0; c < 4; c++) {
                unsigned m = bg[c];
                while (m) {
                    const int b = __ffs(m) - 1;
                    m &= m - 1;
                    const int j = (b << 2) + c;
                    float e = sv + dst_s[j];
                    e = e > 0.f ? e : ALPHA * e;
                    const float p = __expf(e - px);
                    den[rg] += p;
                    const float4 w0 = *reinterpret_cast<const float4*>(&Whs[j][s << 3]);
                    const float4 w1 = *reinterpret_cast<const float4*>(&Whs[j][(s << 3) + 4]);
                    acc[rg][0] += p * w0.x; acc[rg][1] += p * w0.y;
                    acc[rg][2] += p * w0.z; acc[rg][3] += p * w0.w;
                    acc[rg][4] += p * w1.x; acc[rg][5] += p * w1.y;
                    acc[rg][6] += p * w1.z; acc[rg][7] += p * w1.w;
                }
            }
        }
    }

#pragma unroll
    for (int rg = 0; rg < 2; rg++) {
        const int row = I0 + w * 8 + rg * 4 + g;
        *reinterpret_cast<float4*>(&g_pacc[js][row][s << 3]) =
            make_float4(acc[rg][0], acc[rg][1], acc[rg][2], acc[rg][3]);
        *reinterpret_cast<float4*>(&g_pacc[js][row][(s << 3) + 4]) =
            make_float4(acc[rg][4], acc[rg][5], acc[rg][6], acc[rg][7]);
        if (s == 0) g_pden[js][row] = den[rg];
    }
}

// ---------------------------------------------------------------------------
// Kernel 3: combine column-split partials, normalize, ELU.
// ---------------------------------------------------------------------------
__global__ __launch_bounds__(256) void combine_kernel(float* __restrict__ out) {
    const int idx = blockIdx.x * 256 + threadIdx.x;  // over 8192*64
    const int i = idx >> 6;
    float sum = 0.f, d = 0.f;
#pragma unroll
    for (int js = 0; js < JSPLIT; js++) {
        sum += g_pacc[js][i][idx & 63];
        d   += g_pden[js][i];
    }
    const float v = sum / d;
    out[idx] = v > 0.f ? v : expm1f(v);
}

// ---------------------------------------------------------------------------
// inputs: h [8192,256] f32, adj [8192,8192] f32, W [256,64] f32, a [128,1] f32
// output: [8192,64] f32
// ---------------------------------------------------------------------------
extern "C" void kernel_launch(void* const* d_in, const int* in_sizes, int n_in,
                              void* d_out, int out_size) {
    const float* h   = (const float*)d_in[0];
    const float* adj = (const float*)d_in[1];
    const float* W   = (const float*)d_in[2];
    const float* a   = (const float*)d_in[3];
    float* out = (float*)d_out;

    wh_kernel<<<N_NODES / 64, 256>>>(h, W, a);
    attn_kernel<<<(N_NODES / ROWTILE) * JSPLIT, 512>>>(adj);
    combine_kernel<<<(N_NODES * OUT_F) / 256, 256>>>(out);
}

// round 5
// speedup vs baseline: 1.1821x; 1.1821x over previous
#include <cuda_runtime.h>
#include <cuda_fp16.h>
#include <cstdint>

#define N_NODES 8192
#define IN_F 256
#define OUT_F 64
#define ALPHA 0.3f
#define JSPLIT 8
#define ROWTILE 128
#define KCH 64            // columns (K) per chunk
#define NCHUNK 16         // (8192/JSPLIT)/KCH
#define NWHBLK 256        // wh_kernel blocks (32 rows each)
#define PROW 72           // padded SMEM row stride in halves (144 B)

// ---------------- device scratch (no allocations allowed) ----------------
__device__ __half g_WhT[OUT_F * N_NODES];            // Wh^T fp16 [64][8192], 1 MB
__device__ float g_src[N_NODES];
__device__ float g_dst[N_NODES];
__device__ float g_blockmax[NWHBLK];
__device__ float g_pacc[JSPLIT][N_NODES][OUT_F];     // 16 MB fp32 partials
__device__ float g_pden[JSPLIT][N_NODES];

__device__ __forceinline__ uint32_t smem_u32(const void* p) {
    uint32_t a;
    asm("{ .reg .u64 t; cvta.to.shared.u64 t, %1; cvt.u32.u64 %0, t; }" : "=r"(a) : "l"(p));
    return a;
}
__device__ __forceinline__ void ldmatrix_x4(uint32_t& r0, uint32_t& r1, uint32_t& r2,
                                            uint32_t& r3, uint32_t addr) {
    asm volatile("ldmatrix.sync.aligned.m8n8.x4.shared.b16 {%0,%1,%2,%3}, [%4];"
                 : "=r"(r0), "=r"(r1), "=r"(r2), "=r"(r3) : "r"(addr));
}
__device__ __forceinline__ void mma_16816(float* c, uint32_t a0, uint32_t a1,
                                          uint32_t a2, uint32_t a3,
                                          uint32_t b0, uint32_t b1) {
    asm volatile(
        "mma.sync.aligned.m16n8k16.row.col.f32.f16.f16.f32 "
        "{%0,%1,%2,%3}, {%4,%5,%6,%7}, {%8,%9}, {%0,%1,%2,%3};"
        : "+f"(c[0]), "+f"(c[1]), "+f"(c[2]), "+f"(c[3])
        : "r"(a0), "r"(a1), "r"(a2), "r"(a3), "r"(b0), "r"(b1));
}

// ---------------------------------------------------------------------------
// Kernel 1: Wh = h @ W; outputs WhT fp16 [64][8192], src/dst fp32, per-block
// dst max. Block = 32 rows x 64 feats, 256 threads (2 rows x 4 feats each).
// ---------------------------------------------------------------------------
__global__ __launch_bounds__(256) void wh_kernel(const float* __restrict__ h,
                                                 const float* __restrict__ W,
                                                 const float* __restrict__ a) {
    __shared__ float sh[32][68];
    __shared__ float sW[64][64];
    __shared__ float dtile[32];
    const int tid = threadIdx.x;
    const int tx = tid & 15;        // feat group (4 feats)
    const int ty = tid >> 4;        // row group (2 rows)
    const int I0 = blockIdx.x * 32;

    float acc0[4] = {}, acc1[4] = {};

    for (int kt = 0; kt < 4; kt++) {
        __syncthreads();
#pragma unroll
        for (int it = 0; it < 2; it++) {
            const int s = tid + it * 256;
            const int r = s >> 4, c = (s & 15) << 2;
            *reinterpret_cast<float4*>(&sh[r][c]) = *reinterpret_cast<const float4*>(
                &h[(size_t)(I0 + r) * IN_F + kt * 64 + c]);
        }
#pragma unroll
        for (int it = 0; it < 4; it++) {
            const int s = tid + it * 256;
            const int r = s >> 4, c = (s & 15) << 2;
            *reinterpret_cast<float4*>(&sW[r][c]) = *reinterpret_cast<const float4*>(
                &W[(size_t)(kt * 64 + r) * OUT_F + c]);
        }
        __syncthreads();
#pragma unroll 4
        for (int k = 0; k < 64; k++) {
            const float4 wv = *reinterpret_cast<const float4*>(&sW[k][tx << 2]);
            const float h0 = sh[ty * 2][k], h1 = sh[ty * 2 + 1][k];
            acc0[0] += h0 * wv.x; acc0[1] += h0 * wv.y; acc0[2] += h0 * wv.z; acc0[3] += h0 * wv.w;
            acc1[0] += h1 * wv.x; acc1[1] += h1 * wv.y; acc1[2] += h1 * wv.z; acc1[3] += h1 * wv.w;
        }
    }

#pragma unroll
    for (int ff = 0; ff < 4; ff++) {
        const int f = tx * 4 + ff;
        *reinterpret_cast<__half2*>(&g_WhT[(size_t)f * N_NODES + I0 + ty * 2]) =
            __floats2half2_rn(acc0[ff], acc1[ff]);
    }

    const float4 as = *reinterpret_cast<const float4*>(&a[tx << 2]);
    const float4 ad = *reinterpret_cast<const float4*>(&a[OUT_F + (tx << 2)]);
    float sp0 = acc0[0] * as.x + acc0[1] * as.y + acc0[2] * as.z + acc0[3] * as.w;
    float dp0 = acc0[0] * ad.x + acc0[1] * ad.y + acc0[2] * ad.z + acc0[3] * ad.w;
    float sp1 = acc1[0] * as.x + acc1[1] * as.y + acc1[2] * as.z + acc1[3] * as.w;
    float dp1 = acc1[0] * ad.x + acc1[1] * ad.y + acc1[2] * ad.z + acc1[3] * ad.w;
#pragma unroll
    for (int o = 1; o < 16; o <<= 1) {
        sp0 += __shfl_xor_sync(0xffffffffu, sp0, o);
        dp0 += __shfl_xor_sync(0xffffffffu, dp0, o);
        sp1 += __shfl_xor_sync(0xffffffffu, sp1, o);
        dp1 += __shfl_xor_sync(0xffffffffu, dp1, o);
    }
    if (tx == 0) {
        g_src[I0 + ty * 2] = sp0;     g_src[I0 + ty * 2 + 1] = sp1;
        g_dst[I0 + ty * 2] = dp0;     g_dst[I0 + ty * 2 + 1] = dp1;
        dtile[ty * 2] = dp0;          dtile[ty * 2 + 1] = dp1;
    }
    __syncthreads();
    if (tid == 0) {
        float mm = dtile[0];
        for (int q = 1; q < 32; q++) mm = fmaxf(mm, dtile[q]);
        g_blockmax[blockIdx.x] = mm;
    }
}

// ---------------------------------------------------------------------------
// Kernel 2: masked dense attention GEMM via ldmatrix + mma.sync (HMMA).
// Block = 128 rows x 1024 cols (grid 64 x JSPLIT=8 = 512), 256 threads.
// Per 64-col chunk: P tile fp16 = adj * exp(lrelu(src+dst)-proxy) in SMEM,
// B tile = WhT fp16 in SMEM; warp w accumulates D rows 16w..16w+15 (all 64
// feats) in registers across all 16 chunks. Next chunk's adj is prefetched
// before the MMA phase so DRAM stays busy under the math.
// ---------------------------------------------------------------------------
__global__ __launch_bounds__(256, 2) void attn_kernel(const float* __restrict__ adj) {
    __shared__ __half sP[ROWTILE * PROW];     // 18432 B
    __shared__ __half sB[OUT_F * PROW];       //  9216 B
    __shared__ float sBm[8];
    __shared__ float sDmax;

    const int tid = threadIdx.x;
    const int w = tid >> 5, lane = tid & 31;
    const int q = tid & 15, r0 = tid >> 4;    // P-gen: cols q*4.., rows r0+16m
    const int rt = blockIdx.x >> 3, js = blockIdx.x & 7;
    const int I0 = rt * ROWTILE;
    const int jbase = js * (N_NODES / JSPLIT);

    // dmax over g_blockmax[256]
    {
        float m = g_blockmax[tid];
#pragma unroll
        for (int o = 16; o; o >>= 1) m = fmaxf(m, __shfl_xor_sync(0xffffffffu, m, o));
        if (lane == 0) sBm[w] = m;
    }
    __syncthreads();
    if (tid == 0) {
        float mm = sBm[0];
        for (int s = 1; s < 8; s++) mm = fmaxf(mm, sBm[s]);
        sDmax = mm;
    }
    __syncthreads();
    const float dmax = sDmax;

    float srcv[8], proxy[8], den[8];
#pragma unroll
    for (int m8 = 0; m8 < 8; m8++) {
        const float s = __ldg(&g_src[I0 + r0 + 16 * m8]);
        srcv[m8] = s;
        const float e = s + dmax;
        proxy[m8] = e > 0.f ? e : ALPHA * e;
        den[m8] = 0.f;
    }

    // precomputed SMEM addresses for ldmatrix (fragment-pattern lanes)
    const uint32_t pbase = smem_u32(sP);
    const uint32_t bbase = smem_u32(sB);
    const uint32_t aAddr = pbase + ((16 * w + (lane & 15)) * PROW + (lane >> 4) * 8) * 2;
    const uint32_t bRow = (lane & 7) + ((lane & 16) ? 8 : 0);   // within nt-pair
    const uint32_t bKoff = (lane & 8) ? 8 : 0;
    const uint32_t bAddr0 = bbase + (bRow * PROW + bKoff) * 2;

    float acc[8][4] = {};

    // prefetch chunk 0
    float4 av[8];
    float4 dv = __ldg(reinterpret_cast<const float4*>(&g_dst[jbase]) + q);
#pragma unroll
    for (int m8 = 0; m8 < 8; m8++)
        av[m8] = __ldg(reinterpret_cast<const float4*>(
                     &adj[(size_t)(I0 + r0 + 16 * m8) * N_NODES + jbase]) + q);

    for (int ch = 0; ch < NCHUNK; ch++) {
        const int jcol0 = jbase + ch * KCH;

        // ---- P generation (dense, fp16) + den ----
#pragma unroll
        for (int m8 = 0; m8 < 8; m8++) {
            const float sv = srcv[m8], px = proxy[m8];
            float e0 = sv + dv.x, e1 = sv + dv.y, e2 = sv + dv.z, e3 = sv + dv.w;
            e0 = e0 > 0.f ? e0 : ALPHA * e0;  e1 = e1 > 0.f ? e1 : ALPHA * e1;
            e2 = e2 > 0.f ? e2 : ALPHA * e2;  e3 = e3 > 0.f ? e3 : ALPHA * e3;
            const float p0 = av[m8].x * __expf(e0 - px);
            const float p1 = av[m8].y * __expf(e1 - px);
            const float p2 = av[m8].z * __expf(e2 - px);
            const float p3 = av[m8].w * __expf(e3 - px);
            den[m8] += (p0 + p1) + (p2 + p3);
            uint2 pk;
            const __half2 h01 = __floats2half2_rn(p0, p1);
            const __half2 h23 = __floats2half2_rn(p2, p3);
            pk.x = *reinterpret_cast<const uint32_t*>(&h01);
            pk.y = *reinterpret_cast<const uint32_t*>(&h23);
            *reinterpret_cast<uint2*>(&sP[(r0 + 16 * m8) * PROW + q * 4]) = pk;
        }

        // ---- B stage: WhT[f][jcol0..+63] -> sB[f][k], 512 uint4 slots ----
#pragma unroll
        for (int it = 0; it < 2; it++) {
            const int idx = tid + it * 256;
            const int f = idx >> 3, u = idx & 7;
            *reinterpret_cast<uint4*>(&sB[f * PROW + u * 8]) =
                __ldg(reinterpret_cast<const uint4*>(&g_WhT[(size_t)f * N_NODES + jcol0]) + u);
        }
        __syncthreads();

        // ---- prefetch next chunk's adj/dst while MMA runs ----
        if (ch + 1 < NCHUNK) {
            const int jn = jcol0 + KCH;
            dv = __ldg(reinterpret_cast<const float4*>(&g_dst[jn]) + q);
#pragma unroll
            for (int m8 = 0; m8 < 8; m8++)
                av[m8] = __ldg(reinterpret_cast<const float4*>(
                             &adj[(size_t)(I0 + r0 + 16 * m8) * N_NODES + jn]) + q);
        }

        // ---- MMA: warp w does D[16w..16w+15][0..63] += P*B^T ----
#pragma unroll
        for (int kk = 0; kk < 4; kk++) {
            uint32_t a0, a1, a2, a3;
            ldmatrix_x4(a0, a1, a2, a3, aAddr + kk * 32);
#pragma unroll
            for (int np = 0; np < 4; np++) {   // nt pair (2*np, 2*np+1)
                uint32_t b0, b1, b2, b3;
                ldmatrix_x4(b0, b1, b2, b3,
                            bAddr0 + (np * 16 * PROW + kk * 16) * 2);
                mma_16816(acc[2 * np],     a0, a1, a2, a3, b0, b1);
                mma_16816(acc[2 * np + 1], a0, a1, a2, a3, b2, b3);
            }
        }
        __syncthreads();
    }

    // ---- den: reduce over q (16-lane groups) ----
#pragma unroll
    for (int m8 = 0; m8 < 8; m8++) {
        float d = den[m8];
#pragma unroll
        for (int o = 1; o < 16; o <<= 1) d += __shfl_xor_sync(0xffffffffu, d, o);
        if (q == 0) g_pden[js][I0 + r0 + 16 * m8] = d;
    }

    // ---- D epilogue (fragment layout): lane g=l>>2 rows, t=l&3 col pairs ----
    {
        const int g = lane >> 2, t = lane & 3;
        const int row0 = I0 + 16 * w + g;
#pragma unroll
        for (int nt = 0; nt < 8; nt++) {
            const int col = nt * 8 + t * 2;
            *reinterpret_cast<float2*>(&g_pacc[js][row0][col]) =
                make_float2(acc[nt][0], acc[nt][1]);
            *reinterpret_cast<float2*>(&g_pacc[js][row0 + 8][col]) =
                make_float2(acc[nt][2], acc[nt][3]);
        }
    }
}

// ---------------------------------------------------------------------------
// Kernel 3: combine J-split partials, normalize, ELU.
// ---------------------------------------------------------------------------
__global__ __launch_bounds__(256) void combine_kernel(float* __restrict__ out) {
    const int idx = blockIdx.x * 256 + threadIdx.x;  // over 8192*64
    const int i = idx >> 6, f = idx & 63;
    float sum = 0.f, d = 0.f;
#pragma unroll
    for (int js = 0; js < JSPLIT; js++) {
        sum += g_pacc[js][i][f];
        d   += g_pden[js][i];
    }
    const float v = sum / d;
    out[idx] = v > 0.f ? v : expm1f(v);
}

// ---------------------------------------------------------------------------
// inputs: h [8192,256] f32, adj [8192,8192] f32, W [256,64] f32, a [128,1] f32
// output: [8192,64] f32
// ---------------------------------------------------------------------------
extern "C" void kernel_launch(void* const* d_in, const int* in_sizes, int n_in,
                              void* d_out, int out_size) {
    const float* h   = (const float*)d_in[0];
    const float* adj = (const float*)d_in[1];
    const float* W   = (const float*)d_in[2];
    const float* a   = (const float*)d_in[3];
    float* out = (float*)d_out;

    wh_kernel<<<NWHBLK, 256>>>(h, W, a);
    attn_kernel<<<(N_NODES / ROWTILE) * JSPLIT, 256>>>(adj);
    combine_kernel<<<(N_NODES * OUT_F) / 256, 256>>>(out);
}